// round 9
// baseline (speedup 1.0000x reference)
#include <cuda_runtime.h>
#include <math_constants.h>

// DarkChannel single-phase, all-register:
//   channel-min(C=3) -> vertical 15-min (van Herk, float2 regs)
//   -> horizontal 15-min via warp shuffles -> direct STG.64
// No shared memory, no barriers: warps stream loads continuously.
//
// Each warp owns a 48-column output strip, loading 64 columns (float2/lane,
// lanes 0..31 cover strip-8 .. strip+55; lanes 4..27 emit outputs).
//
// img [16,3,1024,1024] f32 -> out [16,1,1024,1024] f32, +inf border erosion.

#define IMG_H 1024
#define IMG_W 1024
#define IMG_B 16
#define CH_STRIDE (IMG_H * IMG_W)
#define YTILE 15
#define NUM_TY 69                     // ceil(1024/15)
#define WSPAN 48                      // output cols per warp
#define NWARPS 11                     // warps per block
#define NTHREADS (NWARPS * 32)        // 352

__device__ __forceinline__ float2 min2(float2 a, float2 b) {
    return make_float2(fminf(a.x, b.x), fminf(a.y, b.y));
}

template <bool CHECKY>
__device__ __forceinline__ float2 cmin2(const float* p, int y, bool vx) {
    if (!vx || (CHECKY && (unsigned)y >= (unsigned)IMG_H)) {
        return make_float2(CUDART_INF_F, CUDART_INF_F);
    }
    const float* r = p + (size_t)y * IMG_W;
    float2 c0 = *reinterpret_cast<const float2*>(r);
    float2 c1 = *reinterpret_cast<const float2*>(r + CH_STRIDE);
    float2 c2 = *reinterpret_cast<const float2*>(r + 2 * CH_STRIDE);
    return min2(min2(c0, c1), c2);
}

// Horizontal 15-window min across the warp, then store (predicated).
// e = this lane's vertically-eroded pair (cols gx, gx+1).
// out.x window = { a1[l-4], pairs l-3..l+3 }, out.y = { pairs l-3..l+3, a0[l+4] }.
__device__ __forceinline__ void emit(float2 e, bool ok, float* op) {
    const unsigned FULL = 0xffffffffu;
    float m  = fminf(e.x, e.y);                         // pair min
    float t1 = fminf(m,  __shfl_down_sync(FULL, m, 1)); // m[l..l+1]
    float t4 = fminf(t1, __shfl_down_sync(FULL, t1, 2)); // m[l..l+3]
    float s  = fminf(t4, __shfl_down_sync(FULL, t4, 3)); // m[l..l+6]
    float w7 = __shfl_up_sync(FULL, s, 3);              // pairs l-3..l+3
    float eL = __shfl_up_sync(FULL, e.y, 4);            // a1 of lane l-4
    float eR = __shfl_down_sync(FULL, e.x, 4);          // a0 of lane l+4

    if (ok) {
        float2 o = make_float2(fminf(w7, eL), fminf(w7, eR));
        *reinterpret_cast<float2*>(op) = o;
    }
}

// Vertical van Herk (window == block == 15) fused with per-row horizontal emit.
template <bool CHECKY>
__device__ __forceinline__ void strip(const float* p, bool vx, int y0,
                                      bool oc, float* op) {
    float2 h[YTILE];
#pragma unroll
    for (int t = 0; t < YTILE; ++t) {
        h[t] = cmin2<CHECKY>(p, y0 - 7 + t, vx);        // rows y0-7 .. y0+7
    }
#pragma unroll
    for (int t = YTILE - 2; t >= 0; --t) {
        h[t] = min2(h[t], h[t + 1]);                    // suffix mins
    }

    emit(h[0], oc, op);

    float2 g = make_float2(CUDART_INF_F, CUDART_INF_F);
#pragma unroll
    for (int r = 1; r < YTILE; ++r) {
        g = min2(g, cmin2<CHECKY>(p, y0 + 7 + r, vx));  // next-block prefix
        const bool rok = !CHECKY || (y0 + r < IMG_H);
        emit(min2(h[r], g), oc && rok, op + (size_t)r * IMG_W);
    }
}

extern "C" __global__ __launch_bounds__(NTHREADS)
void k_fused(const float* __restrict__ img, float* __restrict__ out) {
    const int lane = threadIdx.x & 31;
    const int wid  = threadIdx.x >> 5;
    const int ws   = blockIdx.x * NWARPS + wid;         // warp strip 0..21
    const int ty   = blockIdx.y;
    const int b    = blockIdx.z;
    const int y0   = ty * YTILE;

    const int gx = ws * WSPAN - 8 + (lane << 1);        // this lane's column pair
    const bool vx = (unsigned)gx < (unsigned)IMG_W;
    const bool oc = (lane >= 4) && (lane < 28) && vx;   // output-lane predicate

    const float* p = img + (size_t)b * 3 * CH_STRIDE + gx;
    float* op = out + ((size_t)b * IMG_H + y0) * IMG_W + gx;

    if (ty >= 1 && ty <= 66) {
        strip<false>(p, vx, y0, oc, op);                // rows y0-7..y0+21 in range
    } else {
        strip<true>(p, vx, y0, oc, op);
    }
}

extern "C" void kernel_launch(void* const* d_in, const int* in_sizes, int n_in,
                              void* d_out, int out_size) {
    const float* img = (const float*)d_in[0];
    float* out = (float*)d_out;

    // 22 warp strips of 48 cols (= 1056 >= 1024), 11 warps/block -> grid.x = 2
    dim3 grid(2, NUM_TY, IMG_B);                        // 2 x 69 x 16
    k_fused<<<grid, NTHREADS>>>(img, out);
}

// round 10
// speedup vs baseline: 1.1612x; 1.1612x over previous
#include <cuda_runtime.h>
#include <math_constants.h>

// DarkChannel fused (R4 skeleton, slimmer phase 2):
//   phase 1: channel-min(C=3) + vertical 15-min van Herk (float2/thread) -> smem
//   phase 2: horizontal 15-min, 8 outputs per thread-iteration via
//            suffix/prefix scans over a 24-float span (6 LDS.128 + 2 STG.128)
//
// img [16,3,1024,1024] f32 -> out [16,1,1024,1024] f32, +inf border erosion.

#define IMG_H 1024
#define IMG_W 1024
#define IMG_B 16
#define CH_STRIDE (IMG_H * IMG_W)
#define YTILE 15
#define NUM_TY 69
#define XSPAN 512
#define HALO 8
#define SROW (XSPAN + 2 * HALO)          // 528
#define NTHREADS 288                     // 264 active in phase 1

__device__ __forceinline__ float2 min2(float2 a, float2 b) {
    return make_float2(fminf(a.x, b.x), fminf(a.y, b.y));
}

template <bool CHECKY>
__device__ __forceinline__ float2 cmin2(const float* p, int y, bool vx) {
    if (!vx || (CHECKY && (unsigned)y >= (unsigned)IMG_H)) {
        return make_float2(CUDART_INF_F, CUDART_INF_F);
    }
    const float* r = p + (size_t)y * IMG_W;
    float2 c0 = *reinterpret_cast<const float2*>(r);
    float2 c1 = *reinterpret_cast<const float2*>(r + CH_STRIDE);
    float2 c2 = *reinterpret_cast<const float2*>(r + 2 * CH_STRIDE);
    return min2(min2(c0, c1), c2);
}

// Vertical van Herk (window == block == 15) for one float2 column pair.
template <bool CHECKY>
__device__ __forceinline__ void vert(const float* p, bool vx, int y0, float* s) {
    float2 h[YTILE];
#pragma unroll
    for (int t = 0; t < YTILE; ++t) {
        h[t] = cmin2<CHECKY>(p, y0 - 7 + t, vx);        // rows y0-7 .. y0+7
    }
#pragma unroll
    for (int t = YTILE - 2; t >= 0; --t) {
        h[t] = min2(h[t], h[t + 1]);                    // suffix mins
    }

    *reinterpret_cast<float2*>(&s[0]) = h[0];

    float2 g = make_float2(CUDART_INF_F, CUDART_INF_F);
#pragma unroll
    for (int r = 1; r < YTILE; ++r) {
        g = min2(g, cmin2<CHECKY>(p, y0 + 7 + r, vx));  // next-block prefix
        *reinterpret_cast<float2*>(&s[r * SROW]) = min2(h[r], g);
    }
}

extern "C" __global__ __launch_bounds__(NTHREADS, 4)
void k_fused(const float* __restrict__ img, float* __restrict__ out) {
    __shared__ float sV[YTILE * SROW];                  // 31680 B

    const int tid = threadIdx.x;
    const int bx  = blockIdx.x;                         // x strip 0..1
    const int ty  = blockIdx.y;                         // y tile 0..68
    const int b   = blockIdx.z;
    const int y0  = ty * YTILE;
    const int X0  = bx * XSPAN;

    // ---- Phase 1: vertical erosion of SROW cols (incl. +/-8 halo) ----
    if (tid < SROW / 2) {                               // 264 active
        const int lc = tid << 1;
        const int gx = X0 - HALO + lc;
        const bool vx = (unsigned)gx < (unsigned)IMG_W;
        const float* p = img + (size_t)b * 3 * CH_STRIDE + gx;
        if (ty >= 1 && ty <= 66) {
            vert<false>(p, vx, y0, &sV[lc]);
        } else {
            vert<true>(p, vx, y0, &sV[lc]);
        }
    }

    __syncthreads();

    // ---- Phase 2: horizontal 15-min, 8 outputs per iteration ----
    // f[0..23] = smem cols (x0-8)..(x0+15); out[j] window = f[j+1 .. j+15].
    const int vrows = min(YTILE, IMG_H - y0);
    const int ng = (XSPAN / 8) * vrows;                 // 64 groups per row
    float* outb = out + (size_t)b * IMG_H * IMG_W;

    for (int i = tid; i < ng; i += NTHREADS) {
        const int r = i >> 6;
        const int c = i & 63;
        const float* row = &sV[r * SROW];
        const int base = c << 3;                        // local col of f[0] (x0-8)

        float f[24];
#pragma unroll
        for (int q = 0; q < 6; ++q) {
            float4 v = *reinterpret_cast<const float4*>(&row[base + 4 * q]);
            f[q * 4 + 0] = v.x;
            f[q * 4 + 1] = v.y;
            f[q * 4 + 2] = v.z;
            f[q * 4 + 3] = v.w;
        }

        // suffix scans: S[j] = min(f[j+1 .. 15])
        float S[8];
        S[7] = f[8];
#pragma unroll
        for (int k = 9; k <= 15; ++k) S[7] = fminf(S[7], f[k]);
#pragma unroll
        for (int j = 6; j >= 0; --j) S[j] = fminf(f[j + 1], S[j + 1]);

        // prefix scans: P[j] = min(f[16 .. j+15]), j >= 1
        float o[8];
        o[0] = S[0];
        float P = f[16];
        o[1] = fminf(S[1], P);
#pragma unroll
        for (int j = 2; j < 8; ++j) {
            P = fminf(P, f[j + 15]);
            o[j] = fminf(S[j], P);
        }

        float* op = outb + (size_t)(y0 + r) * IMG_W + X0 + (c << 3);
        *reinterpret_cast<float4*>(op)     = make_float4(o[0], o[1], o[2], o[3]);
        *reinterpret_cast<float4*>(op + 4) = make_float4(o[4], o[5], o[6], o[7]);
    }
}

extern "C" void kernel_launch(void* const* d_in, const int* in_sizes, int n_in,
                              void* d_out, int out_size) {
    const float* img = (const float*)d_in[0];
    float* out = (float*)d_out;

    dim3 grid(IMG_W / XSPAN, NUM_TY, IMG_B);            // 2 x 69 x 16
    k_fused<<<grid, NTHREADS>>>(img, out);
}